// round 6
// baseline (speedup 1.0000x reference)
#include <cuda_runtime.h>

#define B_  16
#define N_  4096
#define S_  1024
#define K_  32
#define M_TOT (B_*S_*K_)   // 524288 rows
#define R2  0.04f
#define OUT_XYZ_ELEMS (B_*S_*3)
#define NC  (B_*S_)        // 16384 centroids

// ---------------- scratch ----------------
__device__ float4 g_xyzw[B_*N_];
__device__ float4 g_cent[NC];
__device__ int    g_gidx[NC*K_];
__device__ unsigned g_mask[128*NC];         // 8MB, [word][centroid] (transposed)
__device__ float  g_y1[(size_t)M_TOT*64];   // 134MB
__device__ float  g_y2[(size_t)M_TOT*64];   // 134MB
__device__ float  g_mx[(size_t)NC*128];     // 8MB
__device__ float  g_mn[(size_t)NC*128];     // 8MB
__device__ float  g_wt1[68*64];             // [k][o], k=67 row zero
__device__ float  g_wt2[64*64];
__device__ float  g_wt3[64*128];
__device__ double g_sum[3*128];
__device__ double g_sq [3*128];
__device__ float  g_scale[3*128];
__device__ float  g_shift[3*128];

__device__ __forceinline__ unsigned fenc(float f) {
    int b = __float_as_int(f);
    return (b >= 0) ? ((unsigned)b | 0x80000000u) : ~(unsigned)b;
}
__device__ __forceinline__ float fdec(unsigned k) {
    int b = (k & 0x80000000u) ? (int)(k & 0x7fffffffu) : ~(int)k;
    return __int_as_float(b);
}

// ---------------- prep: pack xyz + |p|^2 ----------------
__global__ void prep_kernel(const float* __restrict__ xyz) {
    int i = blockIdx.x * 256 + threadIdx.x;
    if (i < B_*N_) {
        float x = xyz[3*i], y = xyz[3*i+1], z = xyz[3*i+2];
        float ss = __fadd_rn(__fadd_rn(__fmul_rn(x,x), __fmul_rn(y,y)), __fmul_rn(z,z));
        g_xyzw[i] = make_float4(x, y, z, ss);
    }
}

// ---------------- wprep: transpose weights, zero stats ----------------
__global__ void wprep_kernel(const float* __restrict__ w1,
                             const float* __restrict__ w2,
                             const float* __restrict__ w3) {
    int tid = blockIdx.x * 256 + threadIdx.x;
    int stride = gridDim.x * 256;
    for (int i = tid; i < 3*128; i += stride) { g_sum[i] = 0.0; g_sq[i] = 0.0; }
    for (int i = tid; i < 68*64; i += stride) {
        int k = i >> 6, o = i & 63;
        g_wt1[i] = (k < 67) ? w1[o*67 + k] : 0.f;
    }
    for (int i = tid; i < 64*64; i += stride) {
        int k = i >> 6, o = i & 63;
        g_wt2[i] = w2[o*64 + k];
    }
    for (int i = tid; i < 64*128; i += stride) {
        int k = i >> 7, o = i & 127;
        g_wt3[i] = w3[o*64 + k];
    }
}

// ---------------- FPS: 256 thr x 16 pts, redux-based argmax ----------------
__global__ __launch_bounds__(256) void fps_kernel(float* __restrict__ out) {
    int b = blockIdx.x, tid = threadIdx.x;
    int lane = tid & 31, wid = tid >> 5;
    __shared__ unsigned svu[2][8];
    __shared__ unsigned siu[2][8];
    const float4* base = g_xyzw + b * N_;

    float px[16], py[16], pz[16], d[16];
#pragma unroll
    for (int j = 0; j < 16; j++) {
        float4 p = base[tid*16 + j];
        px[j] = p.x; py[j] = p.y; pz[j] = p.z; d[j] = 1e10f;
    }
    float4 c0 = base[0];
    float cx = c0.x, cy = c0.y, cz = c0.z;
    if (tid == 0) {
        float* o = out + (size_t)(b*S_)*3;
        o[0] = cx; o[1] = cy; o[2] = cz;
        float cs = __fadd_rn(__fadd_rn(__fmul_rn(cx,cx), __fmul_rn(cy,cy)), __fmul_rn(cz,cz));
        g_cent[b*S_] = make_float4(cx, cy, cz, cs);
    }
    int p = 0;
    for (int it = 1; it < S_; ++it) {
        float bestv = -1.0f; int besti = 0;
#pragma unroll
        for (int j = 0; j < 16; j++) {
            float dx = px[j] - cx, dy = py[j] - cy, dz = pz[j] - cz;
            float dd = __fadd_rn(__fadd_rn(__fmul_rn(dx,dx), __fmul_rn(dy,dy)), __fmul_rn(dz,dz));
            d[j] = fminf(d[j], dd);
            if (d[j] > bestv) { bestv = d[j]; besti = tid*16 + j; }
        }
        // warp argmax: d >= 0 so float bits order == uint order
        unsigned vb = __float_as_uint(bestv);
        unsigned mx = __reduce_max_sync(0xffffffffu, vb);
        unsigned ib = (vb == mx) ? (unsigned)besti : 0xffffffffu;
        unsigned im = __reduce_min_sync(0xffffffffu, ib);
        if (lane == 0) { svu[p][wid] = mx; siu[p][wid] = im; }
        __syncthreads();
        unsigned wv = svu[p][0], wi = siu[p][0];
#pragma unroll
        for (int w = 1; w < 8; w++) {
            unsigned v = svu[p][w], ii = siu[p][w];
            if (v > wv || (v == wv && ii < wi)) { wv = v; wi = ii; }
        }
        float4 cc = base[wi];
        cx = cc.x; cy = cc.y; cz = cc.z;
        if (tid == 0) {
            float* o = out + (size_t)(b*S_ + it)*3;
            o[0] = cx; o[1] = cy; o[2] = cz;
            float cs = __fadd_rn(__fadd_rn(__fmul_rn(cx,cx), __fmul_rn(cy,cy)), __fmul_rn(cz,cz));
            g_cent[b*S_ + it] = make_float4(cx, cy, cz, cs);
        }
        p ^= 1;
    }
}

// ---------------- ballq phase A: membership bitmask, warp-per-(cent,word) ----------------
// grid: b(16) x chunk(4) x cgroup(16)  -> 1024 blocks, 256 threads
__global__ __launch_bounds__(256) void ballq_mask_kernel() {
    __shared__ float4 pts_s[1024];   // 16KB point chunk
    int blk = blockIdx.x;
    int b     = blk >> 6;
    int chunk = (blk >> 4) & 3;
    int cg    = blk & 15;
    int tid = threadIdx.x;
    int lane = tid & 31, w = tid >> 5;
    const float4* base = g_xyzw + b*N_ + chunk*1024;
#pragma unroll
    for (int r = 0; r < 4; r++) pts_s[tid + r*256] = base[tid + r*256];
    __syncthreads();
#pragma unroll
    for (int ci = 0; ci < 8; ci++) {
        int m = b*1024 + cg*64 + w*8 + ci;
        float4 c = g_cent[m];   // broadcast across warp
        unsigned* mrow = g_mask + (size_t)(chunk*32)*NC + m;
#pragma unroll 4
        for (int word = 0; word < 32; word++) {
            float4 pt = pts_s[word*32 + lane];
            float dot = __fadd_rn(__fadd_rn(__fmul_rn(c.x,pt.x), __fmul_rn(c.y,pt.y)), __fmul_rn(c.z,pt.z));
            float t = __fmul_rn(-2.0f, dot);
            t = __fadd_rn(t, c.w);
            t = __fadd_rn(t, pt.w);
            unsigned msk = __ballot_sync(0xffffffffu, t <= R2);
            if (lane == 0) mrow[(size_t)word*NC] = msk;
        }
    }
}

// ---------------- ballq phase B: extract first K set bits in order ----------------
__global__ __launch_bounds__(256) void ballq_extract_kernel() {
    int m = blockIdx.x * 256 + threadIdx.x;   // NC threads
    int* gout = g_gidx + m * K_;
    int cnt = 0, first = 0;
    for (int i = 0; i < 128; i++) {
        unsigned wmask = g_mask[(size_t)i*NC + m];   // coalesced across threads
        while (wmask) {
            int bit = __ffs(wmask) - 1;
            wmask &= wmask - 1;
            int n = i*32 + bit;
            if (cnt == 0) first = n;
            gout[cnt] = n;
            if (++cnt == K_) break;
        }
        if (cnt == K_) break;
    }
    for (int j = cnt; j < K_; j++) gout[j] = first;
}

// ---------------- conv1: gather + 64x128x68 GEMM, 8x8 microtile ----------------
__global__ __launch_bounds__(128) void conv1_kernel(const float* __restrict__ pts,
                                                    const float* __restrict__ bias) {
    __shared__ float fs[68*128];
    __shared__ float ws[17*64];
    __shared__ float ssum[64], ssq[64];
    int blk = blockIdx.x, tid = threadIdx.x;
    if (tid < 64) { ssum[tid] = 0.f; ssq[tid] = 0.f; }

    float rw[9];
#pragma unroll
    for (int r = 0; r < 9; r++) {
        int i = r*128 + tid;
        rw[r] = (i < 17*64) ? g_wt1[i] : 0.f;
    }

    {   // gather: one sample row per thread
        int m = blk*4 + (tid >> 5);
        int ks = tid & 31;
        int b = m >> 10;
        int idx = g_gidx[m*K_ + ks];
        float4 cen = g_cent[m];
        float4 pp  = g_xyzw[b*N_ + idx];
        fs[0*128 + tid]  = pp.x - cen.x;
        fs[1*128 + tid]  = pp.y - cen.y;
        fs[2*128 + tid]  = pp.z - cen.z;
        fs[67*128 + tid] = 0.f;
        const float4* prow = (const float4*)(pts + ((size_t)(b*N_ + idx))*64);
#pragma unroll
        for (int c4 = 0; c4 < 16; c4++) {
            float4 v = prow[c4];
            int c = 3 + c4*4;
            fs[(c+0)*128 + tid] = v.x;
            fs[(c+1)*128 + tid] = v.y;
            fs[(c+2)*128 + tid] = v.z;
            fs[(c+3)*128 + tid] = v.w;
        }
    }

    int ty = tid & 7, tx = tid >> 3;
    int o0 = ty*8, n0 = tx*8;
    float acc[8][8];
#pragma unroll
    for (int i = 0; i < 8; i++) {
        float bv = bias[o0 + i];
#pragma unroll
        for (int j = 0; j < 8; j++) acc[i][j] = bv;
    }
    __syncthreads();

    for (int kc = 0; kc < 4; kc++) {
#pragma unroll
        for (int r = 0; r < 9; r++) {
            int i = r*128 + tid;
            if (i < 17*64) ws[i] = rw[r];
        }
        __syncthreads();
        if (kc < 3) {
#pragma unroll
            for (int r = 0; r < 9; r++) {
                int i = r*128 + tid;
                rw[r] = (i < 17*64) ? g_wt1[(kc+1)*17*64 + i] : 0.f;
            }
        }
#pragma unroll
        for (int kk = 0; kk < 17; kk++) {
            const float4* ap = (const float4*)&ws[kk*64 + o0];
            const float4* bp = (const float4*)&fs[(kc*17 + kk)*128 + n0];
            float4 a0 = ap[0], a1 = ap[1];
            float4 b0 = bp[0], b1 = bp[1];
            float a[8] = {a0.x,a0.y,a0.z,a0.w,a1.x,a1.y,a1.z,a1.w};
            float b[8] = {b0.x,b0.y,b0.z,b0.w,b1.x,b1.y,b1.z,b1.w};
#pragma unroll
            for (int i = 0; i < 8; i++)
#pragma unroll
                for (int j = 0; j < 8; j++)
                    acc[i][j] += a[i]*b[j];
        }
        __syncthreads();
    }

    size_t rowbase = (size_t)blk*128;
#pragma unroll
    for (int j = 0; j < 8; j++) {
        float* yp = g_y1 + (rowbase + n0 + j)*64 + o0;
        *(float4*)yp       = make_float4(acc[0][j], acc[1][j], acc[2][j], acc[3][j]);
        *(float4*)(yp + 4) = make_float4(acc[4][j], acc[5][j], acc[6][j], acc[7][j]);
    }
#pragma unroll
    for (int i = 0; i < 8; i++) {
        float s = 0.f, q = 0.f;
#pragma unroll
        for (int j = 0; j < 8; j++) { s += acc[i][j]; q += acc[i][j]*acc[i][j]; }
        atomicAdd(&ssum[o0+i], s);
        atomicAdd(&ssq [o0+i], q);
    }
    __syncthreads();
    if (tid < 64) {
        atomicAdd(&g_sum[tid], (double)ssum[tid]);
        atomicAdd(&g_sq [tid], (double)ssq[tid]);
    }
}

// ---------------- conv2: bnrelu(y1) -> 64x128x64 GEMM ----------------
__global__ __launch_bounds__(128) void conv2_kernel(const float* __restrict__ bias) {
    __shared__ float fs[64*128];
    __shared__ float ws[16*64];
    __shared__ float scs[64], shs[64];
    __shared__ float ssum[64], ssq[64];
    int blk = blockIdx.x, tid = threadIdx.x;
    if (tid < 64) {
        scs[tid] = g_scale[tid]; shs[tid] = g_shift[tid];
        ssum[tid] = 0.f; ssq[tid] = 0.f;
    }
    float rw[8];
#pragma unroll
    for (int r = 0; r < 8; r++) rw[r] = g_wt2[r*128 + tid];
    __syncthreads();   // scs ready
    {
        const float4* yp = (const float4*)(g_y1 + ((size_t)blk*128 + tid)*64);
#pragma unroll
        for (int c4 = 0; c4 < 16; c4++) {
            float4 v = yp[c4];
            int c = c4*4;
            fs[(c+0)*128+tid] = fmaxf(v.x*scs[c+0]+shs[c+0], 0.f);
            fs[(c+1)*128+tid] = fmaxf(v.y*scs[c+1]+shs[c+1], 0.f);
            fs[(c+2)*128+tid] = fmaxf(v.z*scs[c+2]+shs[c+2], 0.f);
            fs[(c+3)*128+tid] = fmaxf(v.w*scs[c+3]+shs[c+3], 0.f);
        }
    }
    int ty = tid & 7, tx = tid >> 3;
    int o0 = ty*8, n0 = tx*8;
    float acc[8][8];
#pragma unroll
    for (int i = 0; i < 8; i++) {
        float bv = bias[o0 + i];
#pragma unroll
        for (int j = 0; j < 8; j++) acc[i][j] = bv;
    }
    __syncthreads();

    for (int kc = 0; kc < 4; kc++) {
#pragma unroll
        for (int r = 0; r < 8; r++) ws[r*128 + tid] = rw[r];
        __syncthreads();
        if (kc < 3) {
#pragma unroll
            for (int r = 0; r < 8; r++) rw[r] = g_wt2[(kc+1)*1024 + r*128 + tid];
        }
#pragma unroll
        for (int kk = 0; kk < 16; kk++) {
            const float4* ap = (const float4*)&ws[kk*64 + o0];
            const float4* bp = (const float4*)&fs[(kc*16 + kk)*128 + n0];
            float4 a0 = ap[0], a1 = ap[1];
            float4 b0 = bp[0], b1 = bp[1];
            float a[8] = {a0.x,a0.y,a0.z,a0.w,a1.x,a1.y,a1.z,a1.w};
            float b[8] = {b0.x,b0.y,b0.z,b0.w,b1.x,b1.y,b1.z,b1.w};
#pragma unroll
            for (int i = 0; i < 8; i++)
#pragma unroll
                for (int j = 0; j < 8; j++)
                    acc[i][j] += a[i]*b[j];
        }
        __syncthreads();
    }

    size_t rowbase = (size_t)blk*128;
#pragma unroll
    for (int j = 0; j < 8; j++) {
        float* yp = g_y2 + (rowbase + n0 + j)*64 + o0;
        *(float4*)yp       = make_float4(acc[0][j], acc[1][j], acc[2][j], acc[3][j]);
        *(float4*)(yp + 4) = make_float4(acc[4][j], acc[5][j], acc[6][j], acc[7][j]);
    }
#pragma unroll
    for (int i = 0; i < 8; i++) {
        float s = 0.f, q = 0.f;
#pragma unroll
        for (int j = 0; j < 8; j++) { s += acc[i][j]; q += acc[i][j]*acc[i][j]; }
        atomicAdd(&ssum[o0+i], s);
        atomicAdd(&ssq [o0+i], q);
    }
    __syncthreads();
    if (tid < 64) {
        atomicAdd(&g_sum[128 + tid], (double)ssum[tid]);
        atomicAdd(&g_sq [128 + tid], (double)ssq[tid]);
    }
}

// ---------------- conv3: bnrelu(y2) -> 128x128x64 GEMM + per-centroid max/min ----------------
__global__ __launch_bounds__(256) void conv3_kernel(const float* __restrict__ bias) {
    __shared__ float fs[64*128];
    __shared__ float ws[16*128];
    __shared__ float scs[64], shs[64];
    __shared__ float ssum[128], ssq[128];
    __shared__ unsigned smx[4*128], smn[4*128];
    int blk = blockIdx.x, tid = threadIdx.x;
    if (tid < 64) { scs[tid] = g_scale[128+tid]; shs[tid] = g_shift[128+tid]; }
    if (tid < 128) { ssum[tid] = 0.f; ssq[tid] = 0.f; }
#pragma unroll
    for (int r = 0; r < 2; r++) { smx[r*256+tid] = 0u; smn[r*256+tid] = 0xFFFFFFFFu; }
    float rw[8];
#pragma unroll
    for (int r = 0; r < 8; r++) rw[r] = g_wt3[r*256 + tid];
    __syncthreads();
    {
        int n = tid & 127, half = (tid >> 7) * 32;
        const float4* yp = (const float4*)(g_y2 + ((size_t)blk*128 + n)*64 + half);
#pragma unroll
        for (int c4 = 0; c4 < 8; c4++) {
            float4 v = yp[c4];
            int c = half + c4*4;
            fs[(c+0)*128+n] = fmaxf(v.x*scs[c+0]+shs[c+0], 0.f);
            fs[(c+1)*128+n] = fmaxf(v.y*scs[c+1]+shs[c+1], 0.f);
            fs[(c+2)*128+n] = fmaxf(v.z*scs[c+2]+shs[c+2], 0.f);
            fs[(c+3)*128+n] = fmaxf(v.w*scs[c+3]+shs[c+3], 0.f);
        }
    }
    int ty = tid & 15, tx = tid >> 4;
    int o0 = ty*8, n0 = tx*8;
    float acc[8][8];
#pragma unroll
    for (int i = 0; i < 8; i++) {
        float bv = bias[o0 + i];
#pragma unroll
        for (int j = 0; j < 8; j++) acc[i][j] = bv;
    }
    __syncthreads();

    for (int kc = 0; kc < 4; kc++) {
#pragma unroll
        for (int r = 0; r < 8; r++) ws[r*256 + tid] = rw[r];
        __syncthreads();
        if (kc < 3) {
#pragma unroll
            for (int r = 0; r < 8; r++) rw[r] = g_wt3[(kc+1)*2048 + r*256 + tid];
        }
#pragma unroll
        for (int kk = 0; kk < 16; kk++) {
            const float4* ap = (const float4*)&ws[kk*128 + o0];
            const float4* bp = (const float4*)&fs[(kc*16 + kk)*128 + n0];
            float4 a0 = ap[0], a1 = ap[1];
            float4 b0 = bp[0], b1 = bp[1];
            float a[8] = {a0.x,a0.y,a0.z,a0.w,a1.x,a1.y,a1.z,a1.w};
            float b[8] = {b0.x,b0.y,b0.z,b0.w,b1.x,b1.y,b1.z,b1.w};
#pragma unroll
            for (int i = 0; i < 8; i++)
#pragma unroll
                for (int j = 0; j < 8; j++)
                    acc[i][j] += a[i]*b[j];
        }
        __syncthreads();
    }

    int cent = tx >> 2;   // thread's 8 samples live in one centroid
#pragma unroll
    for (int i = 0; i < 8; i++) {
        float s = 0.f, q = 0.f, mx = -3.4e38f, mn = 3.4e38f;
#pragma unroll
        for (int j = 0; j < 8; j++) {
            float v = acc[i][j];
            s += v; q += v*v; mx = fmaxf(mx, v); mn = fminf(mn, v);
        }
        atomicAdd(&ssum[o0+i], s);
        atomicAdd(&ssq [o0+i], q);
        atomicMax(&smx[cent*128 + o0+i], fenc(mx));
        atomicMin(&smn[cent*128 + o0+i], fenc(mn));
    }
    __syncthreads();
    if (tid < 128) {
        atomicAdd(&g_sum[256 + tid], (double)ssum[tid]);
        atomicAdd(&g_sq [256 + tid], (double)ssq[tid]);
    }
#pragma unroll
    for (int r = 0; r < 2; r++) {
        int i = r*256 + tid;
        int c = i >> 7, o = i & 127;
        size_t gi = ((size_t)(blk*4 + c))*128 + o;
        g_mx[gi] = fdec(smx[i]);
        g_mn[gi] = fdec(smn[i]);
    }
}

// ---------------- BN finalize ----------------
__global__ void finalize_kernel(const float* __restrict__ g,
                                const float* __restrict__ beta,
                                int layer, int C) {
    int c = threadIdx.x;
    if (c < C) {
        double mean = g_sum[layer*128 + c] / (double)M_TOT;
        double var  = g_sq [layer*128 + c] / (double)M_TOT - mean*mean;
        float rstd = rsqrtf((float)var + 1e-5f);
        float sc = g[c] * rstd;
        g_scale[layer*128 + c] = sc;
        g_shift[layer*128 + c] = beta[c] - (float)mean * sc;
    }
}

// ---------------- final: BN3 fold + relu + (pre-reduced) max ----------------
__global__ __launch_bounds__(128) void final_kernel(float* __restrict__ out) {
    int m = blockIdx.x, o = threadIdx.x;
    float sc = g_scale[256 + o], sh = g_shift[256 + o];
    size_t gi = (size_t)m*128 + o;
    float y = (sc >= 0.f) ? g_mx[gi] : g_mn[gi];
    out[OUT_XYZ_ELEMS + gi] = fmaxf(y*sc + sh, 0.f);
}

extern "C" void kernel_launch(void* const* d_in, const int* in_sizes, int n_in,
                              void* d_out, int out_size) {
    const float* xyz   = (const float*)d_in[0];
    const float* pts   = (const float*)d_in[1];
    const float* w1    = (const float*)d_in[2];
    const float* b1    = (const float*)d_in[3];
    const float* g1    = (const float*)d_in[4];
    const float* beta1 = (const float*)d_in[5];
    const float* w2    = (const float*)d_in[6];
    const float* b2    = (const float*)d_in[7];
    const float* g2    = (const float*)d_in[8];
    const float* beta2 = (const float*)d_in[9];
    const float* w3    = (const float*)d_in[10];
    const float* b3    = (const float*)d_in[11];
    const float* g3    = (const float*)d_in[12];
    const float* beta3 = (const float*)d_in[13];
    float* out = (float*)d_out;

    prep_kernel<<<(B_*N_ + 255)/256, 256>>>(xyz);
    wprep_kernel<<<32, 256>>>(w1, w2, w3);
    fps_kernel<<<B_, 256>>>(out);
    ballq_mask_kernel<<<1024, 256>>>();
    ballq_extract_kernel<<<NC/256, 256>>>();
    conv1_kernel<<<NC/4, 128>>>(pts, b1);
    finalize_kernel<<<1, 128>>>(g1, beta1, 0, 64);
    conv2_kernel<<<NC/4, 128>>>(b2);
    finalize_kernel<<<1, 128>>>(g2, beta2, 1, 64);
    conv3_kernel<<<NC/4, 256>>>(b3);
    finalize_kernel<<<1, 128>>>(g3, beta3, 2, 128);
    final_kernel<<<NC, 128>>>(out);
}

// round 10
// speedup vs baseline: 1.1084x; 1.1084x over previous
#include <cuda_runtime.h>
#include <cuda_bf16.h>
#include <cstdint>

#define B_  16
#define N_  4096
#define S_  1024
#define K_  32
#define M_TOT (B_*S_*K_)
#define R2  0.04f
#define OUT_XYZ_ELEMS (B_*S_*3)
#define NC  (B_*S_)

// ---------------- scratch ----------------
__device__ float4 g_xyzw[B_*N_];
__device__ float4 g_cent[NC];
__device__ int    g_gidx[NC*K_];
__device__ unsigned g_mask[128*NC];
__device__ float  g_y1[(size_t)M_TOT*64];   // 134MB
__device__ float  g_y2[(size_t)M_TOT*64];   // 134MB
__device__ float  g_mx[(size_t)NC*128];
__device__ float  g_mn[(size_t)NC*128];
// pre-split bf16 weights, padded pitches (elements): w1: 64x88, w2: 64x72, w3: 128x72
__device__ __align__(16) __nv_bfloat16 g_w1s[2][64*88];
__device__ __align__(16) __nv_bfloat16 g_w2s[2][64*72];
__device__ __align__(16) __nv_bfloat16 g_w3s[2][128*72];
__device__ double g_sum[3*128];
__device__ double g_sq [3*128];
__device__ float  g_scale[3*128];
__device__ float  g_shift[3*128];

__device__ __forceinline__ unsigned fenc(float f) {
    int b = __float_as_int(f);
    return (b >= 0) ? ((unsigned)b | 0x80000000u) : ~(unsigned)b;
}
__device__ __forceinline__ float fdec(unsigned k) {
    int b = (k & 0x80000000u) ? (int)(k & 0x7fffffffu) : ~(int)k;
    return __int_as_float(b);
}
__device__ __forceinline__ uint32_t su32(const void* p) {
    uint32_t a;
    asm("{ .reg .u64 t; cvta.to.shared.u64 t, %1; cvt.u32.u64 %0, t; }" : "=r"(a) : "l"(p));
    return a;
}
__device__ __forceinline__ void ldsm4(uint32_t& r0, uint32_t& r1, uint32_t& r2, uint32_t& r3, uint32_t addr) {
    asm volatile("ldmatrix.sync.aligned.m8n8.x4.shared.b16 {%0,%1,%2,%3}, [%4];"
                 : "=r"(r0), "=r"(r1), "=r"(r2), "=r"(r3) : "r"(addr));
}
__device__ __forceinline__ void mma_bf16(float* c, const uint32_t* a, uint32_t b0, uint32_t b1) {
    asm volatile("mma.sync.aligned.m16n8k16.row.col.f32.bf16.bf16.f32 "
                 "{%0,%1,%2,%3}, {%4,%5,%6,%7}, {%8,%9}, {%0,%1,%2,%3};"
                 : "+f"(c[0]), "+f"(c[1]), "+f"(c[2]), "+f"(c[3])
                 : "r"(a[0]), "r"(a[1]), "r"(a[2]), "r"(a[3]), "r"(b0), "r"(b1));
}
__device__ __forceinline__ float rsum(float v) {
    v += __shfl_down_sync(0xffffffffu, v, 16);
    v += __shfl_down_sync(0xffffffffu, v, 8);
    v += __shfl_down_sync(0xffffffffu, v, 4);
    return v;
}
__device__ __forceinline__ float rmaxw(float v) {
    v = fmaxf(v, __shfl_down_sync(0xffffffffu, v, 16));
    v = fmaxf(v, __shfl_down_sync(0xffffffffu, v, 8));
    v = fmaxf(v, __shfl_down_sync(0xffffffffu, v, 4));
    return v;
}
__device__ __forceinline__ float rminw(float v) {
    v = fminf(v, __shfl_down_sync(0xffffffffu, v, 16));
    v = fminf(v, __shfl_down_sync(0xffffffffu, v, 8));
    v = fminf(v, __shfl_down_sync(0xffffffffu, v, 4));
    return v;
}
__device__ __forceinline__ void split_pair(float x, float y, uint32_t& hi, uint32_t& lo) {
    __nv_bfloat16 hx = __float2bfloat16_rn(x);
    __nv_bfloat16 hy = __float2bfloat16_rn(y);
    __nv_bfloat16 lx = __float2bfloat16_rn(x - __bfloat162float(hx));
    __nv_bfloat16 ly = __float2bfloat16_rn(y - __bfloat162float(hy));
    hi = ((uint32_t)(*(uint16_t*)&hy) << 16) | (*(uint16_t*)&hx);
    lo = ((uint32_t)(*(uint16_t*)&ly) << 16) | (*(uint16_t*)&lx);
}
__device__ __forceinline__ void split1(float x, __nv_bfloat16& hi, __nv_bfloat16& lo) {
    hi = __float2bfloat16_rn(x);
    lo = __float2bfloat16_rn(x - __bfloat162float(hi));
}

// ---------------- prep ----------------
__global__ void prep_kernel(const float* __restrict__ xyz) {
    int i = blockIdx.x * 256 + threadIdx.x;
    if (i < B_*N_) {
        float x = xyz[3*i], y = xyz[3*i+1], z = xyz[3*i+2];
        float ss = __fadd_rn(__fadd_rn(__fmul_rn(x,x), __fmul_rn(y,y)), __fmul_rn(z,z));
        g_xyzw[i] = make_float4(x, y, z, ss);
    }
}

// ---------------- wprep: split weights into padded [o][c] layouts; zero stats ----------------
// conv1 column permutation: c<64 -> point channel c (w1 k=3+c); c=64..66 -> xyz (k=c-64); c>=67 -> 0
__global__ void wprep_kernel(const float* __restrict__ w1,
                             const float* __restrict__ w2,
                             const float* __restrict__ w3) {
    int tid = blockIdx.x * 256 + threadIdx.x;
    int stride = gridDim.x * 256;
    for (int i = tid; i < 3*128; i += stride) { g_sum[i] = 0.0; g_sq[i] = 0.0; }
    for (int i = tid; i < 64*88; i += stride) {
        int o = i / 88, c = i - o*88;
        float w = 0.f;
        if (c < 64)      w = w1[o*67 + 3 + c];
        else if (c < 67) w = w1[o*67 + (c - 64)];
        __nv_bfloat16 hi, lo; split1(w, hi, lo);
        g_w1s[0][i] = hi; g_w1s[1][i] = lo;
    }
    for (int i = tid; i < 64*72; i += stride) {
        int o = i / 72, c = i - o*72;
        float w = (c < 64) ? w2[o*64 + c] : 0.f;
        __nv_bfloat16 hi, lo; split1(w, hi, lo);
        g_w2s[0][i] = hi; g_w2s[1][i] = lo;
    }
    for (int i = tid; i < 128*72; i += stride) {
        int o = i / 72, c = i - o*72;
        float w = (c < 64) ? w3[o*64 + c] : 0.f;
        __nv_bfloat16 hi, lo; split1(w, hi, lo);
        g_w3s[0][i] = hi; g_w3s[1][i] = lo;
    }
}

// ---------------- FPS ----------------
__global__ __launch_bounds__(256) void fps_kernel(float* __restrict__ out) {
    int b = blockIdx.x, tid = threadIdx.x;
    int lane = tid & 31, wid = tid >> 5;
    __shared__ unsigned svu[2][8];
    __shared__ unsigned siu[2][8];
    const float4* base = g_xyzw + b * N_;

    float px[16], py[16], pz[16], d[16];
#pragma unroll
    for (int j = 0; j < 16; j++) {
        float4 p = base[tid*16 + j];
        px[j] = p.x; py[j] = p.y; pz[j] = p.z; d[j] = 1e10f;
    }
    float4 c0 = base[0];
    float cx = c0.x, cy = c0.y, cz = c0.z;
    if (tid == 0) {
        float* o = out + (size_t)(b*S_)*3;
        o[0] = cx; o[1] = cy; o[2] = cz;
        float cs = __fadd_rn(__fadd_rn(__fmul_rn(cx,cx), __fmul_rn(cy,cy)), __fmul_rn(cz,cz));
        g_cent[b*S_] = make_float4(cx, cy, cz, cs);
    }
    int p = 0;
    for (int it = 1; it < S_; ++it) {
        float bestv = -1.0f; int besti = 0;
#pragma unroll
        for (int j = 0; j < 16; j++) {
            float dx = px[j] - cx, dy = py[j] - cy, dz = pz[j] - cz;
            float dd = __fadd_rn(__fadd_rn(__fmul_rn(dx,dx), __fmul_rn(dy,dy)), __fmul_rn(dz,dz));
            d[j] = fminf(d[j], dd);
            if (d[j] > bestv) { bestv = d[j]; besti = tid*16 + j; }
        }
        unsigned vb = __float_as_uint(bestv);
        unsigned mx = __reduce_max_sync(0xffffffffu, vb);
        unsigned ib = (vb == mx) ? (unsigned)besti : 0xffffffffu;
        unsigned im = __reduce_min_sync(0xffffffffu, ib);
        if (lane == 0) { svu[p][wid] = mx; siu[p][wid] = im; }
        __syncthreads();
        unsigned wv = svu[p][0], wi = siu[p][0];
#pragma unroll
        for (int w = 1; w < 8; w++) {
            unsigned v = svu[p][w], ii = siu[p][w];
            if (v > wv || (v == wv && ii < wi)) { wv = v; wi = ii; }
        }
        float4 cc = base[wi];
        cx = cc.x; cy = cc.y; cz = cc.z;
        if (tid == 0) {
            float* o = out + (size_t)(b*S_ + it)*3;
            o[0] = cx; o[1] = cy; o[2] = cz;
            float cs = __fadd_rn(__fadd_rn(__fmul_rn(cx,cx), __fmul_rn(cy,cy)), __fmul_rn(cz,cz));
            g_cent[b*S_ + it] = make_float4(cx, cy, cz, cs);
        }
        p ^= 1;
    }
}

// ---------------- ballq phase A ----------------
__global__ __launch_bounds__(256) void ballq_mask_kernel() {
    __shared__ float4 pts_s[1024];
    int blk = blockIdx.x;
    int b     = blk >> 6;
    int chunk = (blk >> 4) & 3;
    int cg    = blk & 15;
    int tid = threadIdx.x;
    int lane = tid & 31, w = tid >> 5;
    const float4* base = g_xyzw + b*N_ + chunk*1024;
#pragma unroll
    for (int r = 0; r < 4; r++) pts_s[tid + r*256] = base[tid + r*256];
    __syncthreads();
#pragma unroll
    for (int ci = 0; ci < 8; ci++) {
        int m = b*1024 + cg*64 + w*8 + ci;
        float4 c = g_cent[m];
        unsigned* mrow = g_mask + (size_t)(chunk*32)*NC + m;
#pragma unroll 4
        for (int word = 0; word < 32; word++) {
            float4 pt = pts_s[word*32 + lane];
            float dot = __fadd_rn(__fadd_rn(__fmul_rn(c.x,pt.x), __fmul_rn(c.y,pt.y)), __fmul_rn(c.z,pt.z));
            float t = __fmul_rn(-2.0f, dot);
            t = __fadd_rn(t, c.w);
            t = __fadd_rn(t, pt.w);
            unsigned msk = __ballot_sync(0xffffffffu, t <= R2);
            if (lane == 0) mrow[(size_t)word*NC] = msk;
        }
    }
}

// ---------------- ballq phase B ----------------
__global__ __launch_bounds__(256) void ballq_extract_kernel() {
    int m = blockIdx.x * 256 + threadIdx.x;
    int* gout = g_gidx + m * K_;
    int cnt = 0, first = 0;
    for (int i = 0; i < 128; i++) {
        unsigned wmask = g_mask[(size_t)i*NC + m];
        while (wmask) {
            int bit = __ffs(wmask) - 1;
            wmask &= wmask - 1;
            int n = i*32 + bit;
            if (cnt == 0) first = n;
            gout[cnt] = n;
            if (++cnt == K_) break;
        }
        if (cnt == K_) break;
    }
    for (int j = cnt; j < K_; j++) gout[j] = first;
}

// ================= conv1: gather -> bf16x3 HMMA (M128,N64,K80), pitch 176B =================
// dyn smem: A_hi 22528, A_lo 22528, B_hi 11264, B_lo 11264 = 67584
__global__ __launch_bounds__(256)
void conv1_kernel(const float* __restrict__ pts, const float* __restrict__ bias) {
    extern __shared__ __align__(16) unsigned char db[];
    __shared__ float ssum[64], ssq[64], bias_s[64];
    const uint32_t A_HI = 0, A_LO = 22528, B_HI = 45056, B_LO = 56320;
    int blk = blockIdx.x, tid = threadIdx.x;
    int lane = tid & 31, w = tid >> 5;
    uint32_t dbase = su32(db);

    if (tid < 64) { ssum[tid] = 0.f; ssq[tid] = 0.f; bias_s[tid] = bias[tid]; }
    {   // copy pre-split weights (704 int4 per split)
        const int4* s0 = (const int4*)g_w1s[0];
        const int4* s1 = (const int4*)g_w1s[1];
        int4* d0 = (int4*)(db + B_HI);
        int4* d1 = (int4*)(db + B_LO);
        for (int i = tid; i < 704; i += 256) { d0[i] = s0[i]; d1[i] = s1[i]; }
    }
    {   // A fill: 2 threads per row; point feats cols 0..63, xyz 64..66, pad 67..79
        int row = tid >> 1, l = tid & 1;
        int m = blk*4 + (row >> 5);
        int b = m >> 10;
        int idx = g_gidx[m*K_ + (row & 31)];
        unsigned char* ah = db + A_HI + row*176;
        unsigned char* al = db + A_LO + row*176;
        const float4* prow = (const float4*)(pts + ((size_t)(b*N_ + idx))*64) + l*8;
#pragma unroll
        for (int j = 0; j < 8; j++) {
            float4 v = prow[j];
            int col = l*32 + j*4;
            uint32_t h01, l01, h23, l23;
            split_pair(v.x, v.y, h01, l01);
            split_pair(v.z, v.w, h23, l23);
            *(uint32_t*)(ah + col*2)     = h01;
            *(uint32_t*)(ah + col*2 + 4) = h23;
            *(uint32_t*)(al + col*2)     = l01;
            *(uint32_t*)(al + col*2 + 4) = l23;
        }
        if (l == 1) {
            float4 cen = g_cent[m];
            float4 pp  = g_xyzw[b*N_ + idx];
            float v3[3] = { pp.x - cen.x, pp.y - cen.y, pp.z - cen.z };
#pragma unroll
            for (int c = 0; c < 3; c++) {
                __nv_bfloat16 hi, lo; split1(v3[c], hi, lo);
                *(__nv_bfloat16*)(ah + (64 + c)*2) = hi;
                *(__nv_bfloat16*)(al + (64 + c)*2) = lo;
            }
            __nv_bfloat16 z = __float2bfloat16_rn(0.f);
            for (int c = 67; c < 80; c++) {
                *(__nv_bfloat16*)(ah + c*2) = z;
                *(__nv_bfloat16*)(al + c*2) = z;
            }
        }
    }
    __syncthreads();

    float acc[8][4];
#pragma unroll
    for (int i = 0; i < 8; i++)
#pragma unroll
        for (int j = 0; j < 4; j++) acc[i][j] = 0.f;

    int g = lane >> 3, ln = lane & 7;
    uint32_t a_off = (uint32_t)(w*16 + ln + (g & 1)*8)*176 + (uint32_t)(g >> 1)*16;
    uint32_t b_off = (uint32_t)(ln + (g >> 1)*8)*176 + (uint32_t)(g & 1)*16;

#pragma unroll
    for (int t = 0; t < 3; t++) {
        uint32_t Ab = dbase + (t == 2 ? A_LO : A_HI) + a_off;
        uint32_t Bb = dbase + (t == 1 ? B_LO : B_HI) + b_off;
#pragma unroll
        for (int ks = 0; ks < 5; ks++) {
            uint32_t a[4];
            ldsm4(a[0], a[1], a[2], a[3], Ab + ks*32);
#pragma unroll
            for (int np = 0; np < 4; np++) {
                uint32_t b0, b1, b2, b3;
                ldsm4(b0, b1, b2, b3, Bb + (uint32_t)np*16*176 + ks*32);
                mma_bf16(acc[2*np],     a, b0, b1);
                mma_bf16(acc[2*np + 1], a, b2, b3);
            }
        }
    }

    // epilogue: bias + y1 + stats
    int q = lane & 3, rr = lane >> 2;
    int rbase = blk*128 + w*16 + rr;
#pragma unroll
    for (int nt = 0; nt < 8; nt++) {
        int c0 = nt*8 + q*2;
        float b0v = bias_s[c0], b1v = bias_s[c0+1];
        float v0 = acc[nt][0] + b0v, v1 = acc[nt][1] + b1v;
        float v2 = acc[nt][2] + b0v, v3 = acc[nt][3] + b1v;
        *(float2*)&g_y1[(size_t)rbase*64 + c0]       = make_float2(v0, v1);
        *(float2*)&g_y1[(size_t)(rbase + 8)*64 + c0] = make_float2(v2, v3);
        float s0 = rsum(v0 + v2), s1 = rsum(v1 + v3);
        float q0 = rsum(v0*v0 + v2*v2), q1 = rsum(v1*v1 + v3*v3);
        if (lane < 4) {
            atomicAdd(&ssum[c0], s0);   atomicAdd(&ssum[c0+1], s1);
            atomicAdd(&ssq [c0], q0);   atomicAdd(&ssq [c0+1], q1);
        }
    }
    __syncthreads();
    if (tid < 64) {
        atomicAdd(&g_sum[tid], (double)ssum[tid]);
        atomicAdd(&g_sq [tid], (double)ssq[tid]);
    }
}

// ================= conv2: bnrelu(y1) -> bf16x3 HMMA (M128,N64,K64), pitch 144B =================
// dyn smem: A_hi 18432, A_lo 18432, B_hi 9216, B_lo 9216 = 55296
__global__ __launch_bounds__(256)
void conv2_kernel(const float* __restrict__ bias) {
    extern __shared__ __align__(16) unsigned char db[];
    __shared__ float ssum[64], ssq[64], bias_s[64], scs[64], shs[64];
    const uint32_t A_HI = 0, A_LO = 18432, B_HI = 36864, B_LO = 46080;
    int blk = blockIdx.x, tid = threadIdx.x;
    int lane = tid & 31, w = tid >> 5;
    uint32_t dbase = su32(db);

    if (tid < 64) {
        ssum[tid] = 0.f; ssq[tid] = 0.f; bias_s[tid] = bias[tid];
        scs[tid] = g_scale[tid]; shs[tid] = g_shift[tid];
    }
    {
        const int4* s0 = (const int4*)g_w2s[0];
        const int4* s1 = (const int4*)g_w2s[1];
        int4* d0 = (int4*)(db + B_HI);
        int4* d1 = (int4*)(db + B_LO);
        for (int i = tid; i < 576; i += 256) { d0[i] = s0[i]; d1[i] = s1[i]; }
    }
    __syncthreads();   // scs/shs ready
    {
        int row = tid >> 1, l = tid & 1;
        unsigned char* ah = db + A_HI + row*144;
        unsigned char* al = db + A_LO + row*144;
        const float4* yp = (const float4*)(g_y1 + ((size_t)(blk*128 + row))*64 + l*32);
#pragma unroll
        for (int j = 0; j < 8; j++) {
            float4 v = yp[j];
            int col = l*32 + j*4;
            float a0 = fmaxf(v.x*scs[col]   + shs[col],   0.f);
            float a1 = fmaxf(v.y*scs[col+1] + shs[col+1], 0.f);
            float a2 = fmaxf(v.z*scs[col+2] + shs[col+2], 0.f);
            float a3 = fmaxf(v.w*scs[col+3] + shs[col+3], 0.f);
            uint32_t h01, l01, h23, l23;
            split_pair(a0, a1, h01, l01);
            split_pair(a2, a3, h23, l23);
            *(uint32_t*)(ah + col*2)     = h01;
            *(uint32_t*)(ah + col*2 + 4) = h23;
            *(uint32_t*)(al + col*2)     = l01;
            *(uint32_t*)(al + col*2 + 4) = l23;
        }
    }
    __syncthreads();

    float acc[8][4];
#pragma unroll
    for (int i = 0; i < 8; i++)
#pragma unroll
        for (int j = 0; j < 4; j++) acc[i][j] = 0.f;

    int g = lane >> 3, ln = lane & 7;
    uint32_t a_off = (uint32_t)(w*16 + ln + (g & 1)*8)*144 + (uint32_t)(g >> 1)*16;
    uint32_t b_off = (uint32_t)(ln + (g >> 1)*8)*144 + (uint32_t)(g & 1)*16;

#pragma unroll
    for (int t = 0; t < 3; t++) {
        uint32_t Ab = dbase + (t == 2 ? A_LO : A_HI) + a_off;
        uint32_t Bb = dbase + (t == 1 ? B_LO : B_HI) + b_off;
#pragma unroll
        for (int ks = 0; ks < 4; ks++) {
            uint32_t a[4];
            ldsm4(a[0], a[1], a[2], a[3], Ab + ks*32);
#pragma unroll
            for (int np = 0; np < 4; np++) {
                uint32_t b0, b1, b2, b3;
                ldsm4(b0, b1, b2, b3, Bb + (uint32_t)np*16*144 + ks*32);
                mma_bf16(acc[2*np],     a, b0, b1);
                mma_bf16(acc[2*np + 1], a, b2, b3);
            }
        }
    }

    int q = lane & 3, rr = lane >> 2;
    int rbase = blk*128 + w*16 + rr;
#pragma unroll
    for (int nt = 0; nt < 8; nt++) {
        int c0 = nt*8 + q*2;
        float b0v = bias_s[c0], b1v = bias_s[c0+1];
        float v0 = acc[nt][0] + b0v, v1 = acc[nt][1] + b1v;
        float v2 = acc[nt][2] + b0v, v3 = acc[nt][3] + b1v;
        *(float2*)&g_y2[(size_t)rbase*64 + c0]       = make_float2(v0, v1);
        *(float2*)&g_y2[(size_t)(rbase + 8)*64 + c0] = make_float2(v2, v3);
        float s0 = rsum(v0 + v2), s1 = rsum(v1 + v3);
        float q0 = rsum(v0*v0 + v2*v2), q1 = rsum(v1*v1 + v3*v3);
        if (lane < 4) {
            atomicAdd(&ssum[c0], s0);   atomicAdd(&ssum[c0+1], s1);
            atomicAdd(&ssq [c0], q0);   atomicAdd(&ssq [c0+1], q1);
        }
    }
    __syncthreads();
    if (tid < 64) {
        atomicAdd(&g_sum[128 + tid], (double)ssum[tid]);
        atomicAdd(&g_sq [128 + tid], (double)ssq[tid]);
    }
}

// ================= conv3: bnrelu(y2) -> bf16x3 HMMA (M128,N128,K64) + max/min =================
// dyn smem: A_hi 18432, A_lo 18432, B_hi 18432, B_lo 18432 = 73728
__global__ __launch_bounds__(256)
void conv3_kernel(const float* __restrict__ bias) {
    extern __shared__ __align__(16) unsigned char db[];
    __shared__ float ssum[128], ssq[128], bias_s[128], scs[64], shs[64];
    __shared__ unsigned smx[512], smn[512];
    const uint32_t A_HI = 0, A_LO = 18432, B_HI = 36864, B_LO = 55296;
    int blk = blockIdx.x, tid = threadIdx.x;
    int lane = tid & 31, w = tid >> 5;
    uint32_t dbase = su32(db);

    if (tid < 64) { scs[tid] = g_scale[128+tid]; shs[tid] = g_shift[128+tid]; }
    if (tid < 128) { ssum[tid] = 0.f; ssq[tid] = 0.f; bias_s[tid] = bias[tid]; }
#pragma unroll
    for (int r = 0; r < 2; r++) { smx[r*256 + tid] = 0u; smn[r*256 + tid] = 0xFFFFFFFFu; }
    {
        const int4* s0 = (const int4*)g_w3s[0];
        const int4* s1 = (const int4*)g_w3s[1];
        int4* d0 = (int4*)(db + B_HI);
        int4* d1 = (int4*)(db + B_LO);
        for (int i = tid; i < 1152; i += 256) { d0[i] = s0[i]; d1[i] = s1[i]; }
    }
    __syncthreads();
    {
        int row = tid >> 1, l = tid & 1;
        unsigned char* ah = db + A_HI + row*144;
        unsigned char* al = db + A_LO + row*144;
        const float4* yp = (const float4*)(g_y2 + ((size_t)(blk*128 + row))*64 + l*32);
#pragma unroll
        for (int j = 0; j < 8; j++) {
            float4 v = yp[j];
            int col = l*32 + j*4;
            float a0 = fmaxf(v.x*scs[col]   + shs[col],   0.f);
            float a1 = fmaxf(v.y*scs[col+1] + shs[col+1], 0.f);
            float a2 = fmaxf(v.z*scs[col+2] + shs[col+2], 0.f);
            float a3 = fmaxf(v.w*scs[col+3] + shs[col+3], 0.f);
            uint32_t h01, l01, h23, l23;
            split_pair(a0, a1, h01, l01);
            split_pair(a2, a3, h23, l23);
            *(uint32_t*)(ah + col*2)     = h01;
            *(uint32_t*)(ah + col*2 + 4) = h23;
            *(uint32_t*)(al + col*2)     = l01;
            *(uint32_t*)(al + col*2 + 4) = l23;
        }
    }
    __syncthreads();

    float acc[16][4];
#pragma unroll
    for (int i = 0; i < 16; i++)
#pragma unroll
        for (int j = 0; j < 4; j++) acc[i][j] = 0.f;

    int g = lane >> 3, ln = lane & 7;
    uint32_t a_off = (uint32_t)(w*16 + ln + (g & 1)*8)*144 + (uint32_t)(g >> 1)*16;
    uint32_t b_off = (uint32_t)(ln + (g >> 1)*8)*144 + (uint32_t)(g & 1)*16;

#pragma unroll
    for (int t = 0; t < 3; t++) {
        uint32_t Ab = dbase + (t == 2 ? A_LO : A_HI) + a_off;
        uint32_t Bb = dbase + (t == 1 ? B_LO : B_HI) + b_off;
#pragma unroll
        for (int ks = 0; ks < 4; ks++) {
            uint32_t a[4];
            ldsm4(a[0], a[1], a[2], a[3], Ab + ks*32);
#pragma unroll
            for (int np = 0; np < 8; np++) {
                uint32_t b0, b1, b2, b3;
                ldsm4(b0, b1, b2, b3, Bb + (uint32_t)np*16*144 + ks*32);
                mma_bf16(acc[2*np],     a, b0, b1);
                mma_bf16(acc[2*np + 1], a, b2, b3);
            }
        }
    }

    int q = lane & 3;
    int cb = (w >> 1) * 128;   // centroid within block
#pragma unroll
    for (int nt = 0; nt < 16; nt++) {
        int c0 = nt*8 + q*2;
        float b0v = bias_s[c0], b1v = bias_s[c0+1];
        float v0 = acc[nt][0] + b0v, v1 = acc[nt][1] + b1v;
        float v2 = acc[nt][2] + b0v, v3 = acc[nt][3] + b1v;
        float mx0 = rmaxw(fmaxf(v0, v2)), mx1 = rmaxw(fmaxf(v1, v3));
        float mn0 = rminw(fminf(v0, v2)), mn1 = rminw(fminf(v1, v3));
        float s0 = rsum(v0 + v2), s1 = rsum(v1 + v3);
        float q0 = rsum(v0*v0 + v2*v2), q1 = rsum(v1*v1 + v3*v3);
        if (lane < 4) {
            atomicMax(&smx[cb + c0], fenc(mx0));  atomicMax(&smx[cb + c0 + 1], fenc(mx1));
            atomicMin(&smn[cb + c0], fenc(mn0));  atomicMin(&smn[cb + c0 + 1], fenc(mn1));
            atomicAdd(&ssum[c0], s0);  atomicAdd(&ssum[c0+1], s1);
            atomicAdd(&ssq [c0], q0);  atomicAdd(&ssq [c0+1], q1);
        }
    }
    __syncthreads();
    if (tid < 128) {
        atomicAdd(&g_sum[256 + tid], (double)ssum[tid]);
        atomicAdd(&g_sq [256 + tid], (double)ssq[tid]);
    }
#pragma unroll
    for (int r = 0; r < 2; r++) {
        int i = r*256 + tid;
        int cent = i >> 7, c = i & 127;
        size_t gi = ((size_t)(blk*4 + cent))*128 + c;
        g_mx[gi] = fdec(smx[i]);
        g_mn[gi] = fdec(smn[i]);
    }
}

// ---------------- BN finalize ----------------
__global__ void finalize_kernel(const float* __restrict__ g,
                                const float* __restrict__ beta,
                                int layer, int C) {
    int c = threadIdx.x;
    if (c < C) {
        double mean = g_sum[layer*128 + c] / (double)M_TOT;
        double var  = g_sq [layer*128 + c] / (double)M_TOT - mean*mean;
        float rstd = rsqrtf((float)var + 1e-5f);
        float sc = g[c] * rstd;
        g_scale[layer*128 + c] = sc;
        g_shift[layer*128 + c] = beta[c] - (float)mean * sc;
    }
}

// ---------------- final ----------------
__global__ __launch_bounds__(128) void final_kernel(float* __restrict__ out) {
    int m = blockIdx.x, o = threadIdx.x;
    float sc = g_scale[256 + o], sh = g_shift[256 + o];
    size_t gi = (size_t)m*128 + o;
    float y = (sc >= 0.f) ? g_mx[gi] : g_mn[gi];
    out[OUT_XYZ_ELEMS + gi] = fmaxf(y*sc + sh, 0.f);
}

extern "C" void kernel_launch(void* const* d_in, const int* in_sizes, int n_in,
                              void* d_out, int out_size) {
    const float* xyz   = (const float*)d_in[0];
    const float* pts   = (const float*)d_in[1];
    const float* w1    = (const float*)d_in[2];
    const float* b1    = (const float*)d_in[3];
    const float* g1    = (const float*)d_in[4];
    const float* beta1 = (const float*)d_in[5];
    const float* w2    = (const float*)d_in[6];
    const float* b2    = (const float*)d_in[7];
    const float* g2    = (const float*)d_in[8];
    const float* beta2 = (const float*)d_in[9];
    const float* w3    = (const float*)d_in[10];
    const float* b3    = (const float*)d_in[11];
    const float* g3    = (const float*)d_in[12];
    const float* beta3 = (const float*)d_in[13];
    float* out = (float*)d_out;

    cudaFuncSetAttribute(conv1_kernel, cudaFuncAttributeMaxDynamicSharedMemorySize, 67584);
    cudaFuncSetAttribute(conv2_kernel, cudaFuncAttributeMaxDynamicSharedMemorySize, 55296);
    cudaFuncSetAttribute(conv3_kernel, cudaFuncAttributeMaxDynamicSharedMemorySize, 73728);

    prep_kernel<<<(B_*N_ + 255)/256, 256>>>(xyz);
    wprep_kernel<<<32, 256>>>(w1, w2, w3);
    fps_kernel<<<B_, 256>>>(out);
    ballq_mask_kernel<<<1024, 256>>>();
    ballq_extract_kernel<<<NC/256, 256>>>();
    conv1_kernel<<<NC/4, 256, 67584>>>(pts, b1);
    finalize_kernel<<<1, 128>>>(g1, beta1, 0, 64);
    conv2_kernel<<<NC/4, 256, 55296>>>(b2);
    finalize_kernel<<<1, 128>>>(g2, beta2, 1, 64);
    conv3_kernel<<<NC/4, 256, 73728>>>(b3);
    finalize_kernel<<<1, 128>>>(g3, beta3, 2, 128);
    final_kernel<<<NC, 128>>>(out);
}

// round 12
// speedup vs baseline: 1.1714x; 1.0569x over previous
#include <cuda_runtime.h>
#include <cuda_bf16.h>
#include <cstdint>

#define B_  16
#define N_  4096
#define S_  1024
#define K_  32
#define M_TOT (B_*S_*K_)
#define R2  0.04f
#define OUT_XYZ_ELEMS (B_*S_*3)
#define NC  (B_*S_)

// ---------------- scratch ----------------
__device__ float4 g_xyzw[B_*N_];
__device__ float4 g_cent[NC];
__device__ int    g_gidx[NC*K_];
__device__ unsigned g_mask[128*NC];
__device__ float  g_y1[(size_t)M_TOT*64];   // 134MB
__device__ float  g_y2[(size_t)M_TOT*64];   // 134MB
__device__ float  g_mx[(size_t)NC*128];
__device__ float  g_mn[(size_t)NC*128];
// pre-split bf16 weights, padded pitches (elements): w1: 64x88, w2: 64x72, w3: 128x72
__device__ __align__(16) __nv_bfloat16 g_w1s[2][64*88];
__device__ __align__(16) __nv_bfloat16 g_w2s[2][64*72];
__device__ __align__(16) __nv_bfloat16 g_w3s[2][128*72];
__device__ double g_sum[3*128];
__device__ double g_sq [3*128];
__device__ float  g_scale[3*128];
__device__ float  g_shift[3*128];

__device__ __forceinline__ unsigned fenc(float f) {
    int b = __float_as_int(f);
    return (b >= 0) ? ((unsigned)b | 0x80000000u) : ~(unsigned)b;
}
__device__ __forceinline__ float fdec(unsigned k) {
    int b = (k & 0x80000000u) ? (int)(k & 0x7fffffffu) : ~(int)k;
    return __int_as_float(b);
}
__device__ __forceinline__ uint32_t su32(const void* p) {
    uint32_t a;
    asm("{ .reg .u64 t; cvta.to.shared.u64 t, %1; cvt.u32.u64 %0, t; }" : "=r"(a) : "l"(p));
    return a;
}
__device__ __forceinline__ void ldsm4(uint32_t& r0, uint32_t& r1, uint32_t& r2, uint32_t& r3, uint32_t addr) {
    asm volatile("ldmatrix.sync.aligned.m8n8.x4.shared.b16 {%0,%1,%2,%3}, [%4];"
                 : "=r"(r0), "=r"(r1), "=r"(r2), "=r"(r3) : "r"(addr));
}
__device__ __forceinline__ void mma_bf16(float* c, const uint32_t* a, uint32_t b0, uint32_t b1) {
    asm volatile("mma.sync.aligned.m16n8k16.row.col.f32.bf16.bf16.f32 "
                 "{%0,%1,%2,%3}, {%4,%5,%6,%7}, {%8,%9}, {%0,%1,%2,%3};"
                 : "+f"(c[0]), "+f"(c[1]), "+f"(c[2]), "+f"(c[3])
                 : "r"(a[0]), "r"(a[1]), "r"(a[2]), "r"(a[3]), "r"(b0), "r"(b1));
}
__device__ __forceinline__ float rsum(float v) {
    v += __shfl_down_sync(0xffffffffu, v, 16);
    v += __shfl_down_sync(0xffffffffu, v, 8);
    v += __shfl_down_sync(0xffffffffu, v, 4);
    return v;
}
__device__ __forceinline__ float rmaxw(float v) {
    v = fmaxf(v, __shfl_down_sync(0xffffffffu, v, 16));
    v = fmaxf(v, __shfl_down_sync(0xffffffffu, v, 8));
    v = fmaxf(v, __shfl_down_sync(0xffffffffu, v, 4));
    return v;
}
__device__ __forceinline__ float rminw(float v) {
    v = fminf(v, __shfl_down_sync(0xffffffffu, v, 16));
    v = fminf(v, __shfl_down_sync(0xffffffffu, v, 8));
    v = fminf(v, __shfl_down_sync(0xffffffffu, v, 4));
    return v;
}
// fast bf16 hi/lo split of a float pair via packed intrinsic (no hand-written PTX).
// __float22bfloat162_rn packs bf16(x) low / bf16(y) high, rounding identical to __float2bfloat16_rn.
__device__ __forceinline__ void split_pair(float x, float y, uint32_t& hi, uint32_t& lo) {
    __nv_bfloat162 h = __float22bfloat162_rn(make_float2(x, y));
    float hx = __bfloat162float(h.x), hy = __bfloat162float(h.y);
    __nv_bfloat162 l = __float22bfloat162_rn(make_float2(x - hx, y - hy));
    hi = *(uint32_t*)&h;
    lo = *(uint32_t*)&l;
}
__device__ __forceinline__ void split1(float x, __nv_bfloat16& hi, __nv_bfloat16& lo) {
    hi = __float2bfloat16_rn(x);
    lo = __float2bfloat16_rn(x - __bfloat162float(hi));
}

// ---------------- prep ----------------
__global__ void prep_kernel(const float* __restrict__ xyz) {
    int i = blockIdx.x * 256 + threadIdx.x;
    if (i < B_*N_) {
        float x = xyz[3*i], y = xyz[3*i+1], z = xyz[3*i+2];
        float ss = __fadd_rn(__fadd_rn(__fmul_rn(x,x), __fmul_rn(y,y)), __fmul_rn(z,z));
        g_xyzw[i] = make_float4(x, y, z, ss);
    }
}

// ---------------- wprep ----------------
__global__ void wprep_kernel(const float* __restrict__ w1,
                             const float* __restrict__ w2,
                             const float* __restrict__ w3) {
    int tid = blockIdx.x * 256 + threadIdx.x;
    int stride = gridDim.x * 256;
    for (int i = tid; i < 3*128; i += stride) { g_sum[i] = 0.0; g_sq[i] = 0.0; }
    for (int i = tid; i < 64*88; i += stride) {
        int o = i / 88, c = i - o*88;
        float w = 0.f;
        if (c < 64)      w = w1[o*67 + 3 + c];
        else if (c < 67) w = w1[o*67 + (c - 64)];
        __nv_bfloat16 hi, lo; split1(w, hi, lo);
        g_w1s[0][i] = hi; g_w1s[1][i] = lo;
    }
    for (int i = tid; i < 64*72; i += stride) {
        int o = i / 72, c = i - o*72;
        float w = (c < 64) ? w2[o*64 + c] : 0.f;
        __nv_bfloat16 hi, lo; split1(w, hi, lo);
        g_w2s[0][i] = hi; g_w2s[1][i] = lo;
    }
    for (int i = tid; i < 128*72; i += stride) {
        int o = i / 72, c = i - o*72;
        float w = (c < 64) ? w3[o*64 + c] : 0.f;
        __nv_bfloat16 hi, lo; split1(w, hi, lo);
        g_w3s[0][i] = hi; g_w3s[1][i] = lo;
    }
}

// ---------------- FPS ----------------
__global__ __launch_bounds__(256) void fps_kernel(float* __restrict__ out) {
    int b = blockIdx.x, tid = threadIdx.x;
    int lane = tid & 31, wid = tid >> 5;
    __shared__ unsigned svu[2][8];
    __shared__ unsigned siu[2][8];
    const float4* base = g_xyzw + b * N_;

    float px[16], py[16], pz[16], d[16];
#pragma unroll
    for (int j = 0; j < 16; j++) {
        float4 p = base[tid*16 + j];
        px[j] = p.x; py[j] = p.y; pz[j] = p.z; d[j] = 1e10f;
    }
    float4 c0 = base[0];
    float cx = c0.x, cy = c0.y, cz = c0.z;
    if (tid == 0) {
        float* o = out + (size_t)(b*S_)*3;
        o[0] = cx; o[1] = cy; o[2] = cz;
        float cs = __fadd_rn(__fadd_rn(__fmul_rn(cx,cx), __fmul_rn(cy,cy)), __fmul_rn(cz,cz));
        g_cent[b*S_] = make_float4(cx, cy, cz, cs);
    }
    int p = 0;
    for (int it = 1; it < S_; ++it) {
        float bestv = -1.0f; int besti = 0;
#pragma unroll
        for (int j = 0; j < 16; j++) {
            float dx = px[j] - cx, dy = py[j] - cy, dz = pz[j] - cz;
            float dd = __fadd_rn(__fadd_rn(__fmul_rn(dx,dx), __fmul_rn(dy,dy)), __fmul_rn(dz,dz));
            d[j] = fminf(d[j], dd);
            if (d[j] > bestv) { bestv = d[j]; besti = tid*16 + j; }
        }
        unsigned vb = __float_as_uint(bestv);
        unsigned mx = __reduce_max_sync(0xffffffffu, vb);
        unsigned ib = (vb == mx) ? (unsigned)besti : 0xffffffffu;
        unsigned im = __reduce_min_sync(0xffffffffu, ib);
        if (lane == 0) { svu[p][wid] = mx; siu[p][wid] = im; }
        __syncthreads();
        unsigned wv = svu[p][0], wi = siu[p][0];
#pragma unroll
        for (int w = 1; w < 8; w++) {
            unsigned v = svu[p][w], ii = siu[p][w];
            if (v > wv || (v == wv && ii < wi)) { wv = v; wi = ii; }
        }
        float4 cc = base[wi];
        cx = cc.x; cy = cc.y; cz = cc.z;
        if (tid == 0) {
            float* o = out + (size_t)(b*S_ + it)*3;
            o[0] = cx; o[1] = cy; o[2] = cz;
            float cs = __fadd_rn(__fadd_rn(__fmul_rn(cx,cx), __fmul_rn(cy,cy)), __fmul_rn(cz,cz));
            g_cent[b*S_ + it] = make_float4(cx, cy, cz, cs);
        }
        p ^= 1;
    }
}

// ---------------- ballq phase A ----------------
__global__ __launch_bounds__(256) void ballq_mask_kernel() {
    __shared__ float4 pts_s[1024];
    int blk = blockIdx.x;
    int b     = blk >> 6;
    int chunk = (blk >> 4) & 3;
    int cg    = blk & 15;
    int tid = threadIdx.x;
    int lane = tid & 31, w = tid >> 5;
    const float4* base = g_xyzw + b*N_ + chunk*1024;
#pragma unroll
    for (int r = 0; r < 4; r++) pts_s[tid + r*256] = base[tid + r*256];
    __syncthreads();
#pragma unroll
    for (int ci = 0; ci < 8; ci++) {
        int m = b*1024 + cg*64 + w*8 + ci;
        float4 c = g_cent[m];
        unsigned* mrow = g_mask + (size_t)(chunk*32)*NC + m;
#pragma unroll 4
        for (int word = 0; word < 32; word++) {
            float4 pt = pts_s[word*32 + lane];
            float dot = __fadd_rn(__fadd_rn(__fmul_rn(c.x,pt.x), __fmul_rn(c.y,pt.y)), __fmul_rn(c.z,pt.z));
            float t = __fmul_rn(-2.0f, dot);
            t = __fadd_rn(t, c.w);
            t = __fadd_rn(t, pt.w);
            unsigned msk = __ballot_sync(0xffffffffu, t <= R2);
            if (lane == 0) mrow[(size_t)word*NC] = msk;
        }
    }
}

// ---------------- ballq phase B ----------------
__global__ __launch_bounds__(256) void ballq_extract_kernel() {
    int m = blockIdx.x * 256 + threadIdx.x;
    int* gout = g_gidx + m * K_;
    int cnt = 0, first = 0;
    for (int i = 0; i < 128; i++) {
        unsigned wmask = g_mask[(size_t)i*NC + m];
        while (wmask) {
            int bit = __ffs(wmask) - 1;
            wmask &= wmask - 1;
            int n = i*32 + bit;
            if (cnt == 0) first = n;
            gout[cnt] = n;
            if (++cnt == K_) break;
        }
        if (cnt == K_) break;
    }
    for (int j = cnt; j < K_; j++) gout[j] = first;
}

// ================= conv1: gather -> bf16x3 HMMA (M128,N64,K80), pitch 176B =================
__global__ __launch_bounds__(256)
void conv1_kernel(const float* __restrict__ pts, const float* __restrict__ bias) {
    extern __shared__ __align__(16) unsigned char db[];
    __shared__ float ssum[64], ssq[64], bias_s[64];
    const uint32_t A_HI = 0, A_LO = 22528, B_HI = 45056, B_LO = 56320;
    int blk = blockIdx.x, tid = threadIdx.x;
    int lane = tid & 31, w = tid >> 5;
    uint32_t dbase = su32(db);

    if (tid < 64) { ssum[tid] = 0.f; ssq[tid] = 0.f; bias_s[tid] = bias[tid]; }
    {
        const int4* s0 = (const int4*)g_w1s[0];
        const int4* s1 = (const int4*)g_w1s[1];
        int4* d0 = (int4*)(db + B_HI);
        int4* d1 = (int4*)(db + B_LO);
        for (int i = tid; i < 704; i += 256) { d0[i] = s0[i]; d1[i] = s1[i]; }
    }
    {   // A fill: 2 threads per row
        int row = tid >> 1, l = tid & 1;
        int m = blk*4 + (row >> 5);
        int b = m >> 10;
        int idx = g_gidx[m*K_ + (row & 31)];
        unsigned char* ah = db + A_HI + row*176;
        unsigned char* al = db + A_LO + row*176;
        const float4* prow = (const float4*)(pts + ((size_t)(b*N_ + idx))*64) + l*8;
#pragma unroll
        for (int j = 0; j < 8; j++) {
            float4 v = prow[j];
            int col = l*32 + j*4;
            uint32_t h01, l01, h23, l23;
            split_pair(v.x, v.y, h01, l01);
            split_pair(v.z, v.w, h23, l23);
            *(uint32_t*)(ah + col*2)     = h01;
            *(uint32_t*)(ah + col*2 + 4) = h23;
            *(uint32_t*)(al + col*2)     = l01;
            *(uint32_t*)(al + col*2 + 4) = l23;
        }
        if (l == 1) {
            float4 cen = g_cent[m];
            float4 pp  = g_xyzw[b*N_ + idx];
            float v3[3] = { pp.x - cen.x, pp.y - cen.y, pp.z - cen.z };
#pragma unroll
            for (int c = 0; c < 3; c++) {
                __nv_bfloat16 hi, lo; split1(v3[c], hi, lo);
                *(__nv_bfloat16*)(ah + (64 + c)*2) = hi;
                *(__nv_bfloat16*)(al + (64 + c)*2) = lo;
            }
            __nv_bfloat16 z = __float2bfloat16_rn(0.f);
            for (int c = 67; c < 80; c++) {
                *(__nv_bfloat16*)(ah + c*2) = z;
                *(__nv_bfloat16*)(al + c*2) = z;
            }
        }
    }
    __syncthreads();

    float acc[8][4];
#pragma unroll
    for (int i = 0; i < 8; i++)
#pragma unroll
        for (int j = 0; j < 4; j++) acc[i][j] = 0.f;

    int g = lane >> 3, ln = lane & 7;
    uint32_t a_off = (uint32_t)(w*16 + ln + (g & 1)*8)*176 + (uint32_t)(g >> 1)*16;
    uint32_t b_off = (uint32_t)(ln + (g >> 1)*8)*176 + (uint32_t)(g & 1)*16;
    uint32_t AbH = dbase + A_HI + a_off, AbL = dbase + A_LO + a_off;
    uint32_t BbH = dbase + B_HI + b_off, BbL = dbase + B_LO + b_off;

#pragma unroll
    for (int ks = 0; ks < 5; ks++) {
        uint32_t ah[4], al[4];
        ldsm4(ah[0], ah[1], ah[2], ah[3], AbH + ks*32);
        ldsm4(al[0], al[1], al[2], al[3], AbL + ks*32);
#pragma unroll
        for (int np = 0; np < 4; np++) {
            uint32_t bh0, bh1, bh2, bh3, bl0, bl1, bl2, bl3;
            ldsm4(bh0, bh1, bh2, bh3, BbH + (uint32_t)np*16*176 + ks*32);
            ldsm4(bl0, bl1, bl2, bl3, BbL + (uint32_t)np*16*176 + ks*32);
            mma_bf16(acc[2*np],     ah, bh0, bh1);
            mma_bf16(acc[2*np + 1], ah, bh2, bh3);
            mma_bf16(acc[2*np],     ah, bl0, bl1);
            mma_bf16(acc[2*np + 1], ah, bl2, bl3);
            mma_bf16(acc[2*np],     al, bh0, bh1);
            mma_bf16(acc[2*np + 1], al, bh2, bh3);
        }
    }

    int q = lane & 3, rr = lane >> 2;
    int rbase = blk*128 + w*16 + rr;
#pragma unroll
    for (int nt = 0; nt < 8; nt++) {
        int c0 = nt*8 + q*2;
        float b0v = bias_s[c0], b1v = bias_s[c0+1];
        float v0 = acc[nt][0] + b0v, v1 = acc[nt][1] + b1v;
        float v2 = acc[nt][2] + b0v, v3 = acc[nt][3] + b1v;
        *(float2*)&g_y1[(size_t)rbase*64 + c0]       = make_float2(v0, v1);
        *(float2*)&g_y1[(size_t)(rbase + 8)*64 + c0] = make_float2(v2, v3);
        float s0 = rsum(v0 + v2), s1 = rsum(v1 + v3);
        float q0 = rsum(v0*v0 + v2*v2), q1 = rsum(v1*v1 + v3*v3);
        if (lane < 4) {
            atomicAdd(&ssum[c0], s0);   atomicAdd(&ssum[c0+1], s1);
            atomicAdd(&ssq [c0], q0);   atomicAdd(&ssq [c0+1], q1);
        }
    }
    __syncthreads();
    if (tid < 64) {
        atomicAdd(&g_sum[tid], (double)ssum[tid]);
        atomicAdd(&g_sq [tid], (double)ssq[tid]);
    }
}

// ================= conv2: bnrelu(y1) -> bf16x3 HMMA (M128,N64,K64), pitch 144B =================
__global__ __launch_bounds__(256)
void conv2_kernel(const float* __restrict__ bias) {
    extern __shared__ __align__(16) unsigned char db[];
    __shared__ float ssum[64], ssq[64], bias_s[64], scs[64], shs[64];
    const uint32_t A_HI = 0, A_LO = 18432, B_HI = 36864, B_LO = 46080;
    int blk = blockIdx.x, tid = threadIdx.x;
    int lane = tid & 31, w = tid >> 5;
    uint32_t dbase = su32(db);

    if (tid < 64) {
        ssum[tid] = 0.f; ssq[tid] = 0.f; bias_s[tid] = bias[tid];
        scs[tid] = g_scale[tid]; shs[tid] = g_shift[tid];
    }
    {
        const int4* s0 = (const int4*)g_w2s[0];
        const int4* s1 = (const int4*)g_w2s[1];
        int4* d0 = (int4*)(db + B_HI);
        int4* d1 = (int4*)(db + B_LO);
        for (int i = tid; i < 576; i += 256) { d0[i] = s0[i]; d1[i] = s1[i]; }
    }
    __syncthreads();
    {
        int row = tid >> 1, l = tid & 1;
        unsigned char* ah = db + A_HI + row*144;
        unsigned char* al = db + A_LO + row*144;
        const float4* yp = (const float4*)(g_y1 + ((size_t)(blk*128 + row))*64 + l*32);
#pragma unroll
        for (int j = 0; j < 8; j++) {
            float4 v = yp[j];
            int col = l*32 + j*4;
            float a0 = fmaxf(v.x*scs[col]   + shs[col],   0.f);
            float a1 = fmaxf(v.y*scs[col+1] + shs[col+1], 0.f);
            float a2 = fmaxf(v.z*scs[col+2] + shs[col+2], 0.f);
            float a3 = fmaxf(v.w*scs[col+3] + shs[col+3], 0.f);
            uint32_t h01, l01, h23, l23;
            split_pair(a0, a1, h01, l01);
            split_pair(a2, a3, h23, l23);
            *(uint32_t*)(ah + col*2)     = h01;
            *(uint32_t*)(ah + col*2 + 4) = h23;
            *(uint32_t*)(al + col*2)     = l01;
            *(uint32_t*)(al + col*2 + 4) = l23;
        }
    }
    __syncthreads();

    float acc[8][4];
#pragma unroll
    for (int i = 0; i < 8; i++)
#pragma unroll
        for (int j = 0; j < 4; j++) acc[i][j] = 0.f;

    int g = lane >> 3, ln = lane & 7;
    uint32_t a_off = (uint32_t)(w*16 + ln + (g & 1)*8)*144 + (uint32_t)(g >> 1)*16;
    uint32_t b_off = (uint32_t)(ln + (g >> 1)*8)*144 + (uint32_t)(g & 1)*16;
    uint32_t AbH = dbase + A_HI + a_off, AbL = dbase + A_LO + a_off;
    uint32_t BbH = dbase + B_HI + b_off, BbL = dbase + B_LO + b_off;

#pragma unroll
    for (int ks = 0; ks < 4; ks++) {
        uint32_t ah[4], al[4];
        ldsm4(ah[0], ah[1], ah[2], ah[3], AbH + ks*32);
        ldsm4(al[0], al[1], al[2], al[3], AbL + ks*32);
#pragma unroll
        for (int np = 0; np < 4; np++) {
            uint32_t bh0, bh1, bh2, bh3, bl0, bl1, bl2, bl3;
            ldsm4(bh0, bh1, bh2, bh3, BbH + (uint32_t)np*16*144 + ks*32);
            ldsm4(bl0, bl1, bl2, bl3, BbL + (uint32_t)np*16*144 + ks*32);
            mma_bf16(acc[2*np],     ah, bh0, bh1);
            mma_bf16(acc[2*np + 1], ah, bh2, bh3);
            mma_bf16(acc[2*np],     ah, bl0, bl1);
            mma_bf16(acc[2*np + 1], ah, bl2, bl3);
            mma_bf16(acc[2*np],     al, bh0, bh1);
            mma_bf16(acc[2*np + 1], al, bh2, bh3);
        }
    }

    int q = lane & 3, rr = lane >> 2;
    int rbase = blk*128 + w*16 + rr;
#pragma unroll
    for (int nt = 0; nt < 8; nt++) {
        int c0 = nt*8 + q*2;
        float b0v = bias_s[c0], b1v = bias_s[c0+1];
        float v0 = acc[nt][0] + b0v, v1 = acc[nt][1] + b1v;
        float v2 = acc[nt][2] + b0v, v3 = acc[nt][3] + b1v;
        *(float2*)&g_y2[(size_t)rbase*64 + c0]       = make_float2(v0, v1);
        *(float2*)&g_y2[(size_t)(rbase + 8)*64 + c0] = make_float2(v2, v3);
        float s0 = rsum(v0 + v2), s1 = rsum(v1 + v3);
        float q0 = rsum(v0*v0 + v2*v2), q1 = rsum(v1*v1 + v3*v3);
        if (lane < 4) {
            atomicAdd(&ssum[c0], s0);   atomicAdd(&ssum[c0+1], s1);
            atomicAdd(&ssq [c0], q0);   atomicAdd(&ssq [c0+1], q1);
        }
    }
    __syncthreads();
    if (tid < 64) {
        atomicAdd(&g_sum[128 + tid], (double)ssum[tid]);
        atomicAdd(&g_sq [128 + tid], (double)ssq[tid]);
    }
}

// ================= conv3: bnrelu(y2) -> bf16x3 HMMA (M128,N128,K64) + max/min =================
__global__ __launch_bounds__(256)
void conv3_kernel(const float* __restrict__ bias) {
    extern __shared__ __align__(16) unsigned char db[];
    __shared__ float ssum[128], ssq[128], bias_s[128], scs[64], shs[64];
    __shared__ unsigned smx[512], smn[512];
    const uint32_t A_HI = 0, A_LO = 18432, B_HI = 36864, B_LO = 55296;
    int blk = blockIdx.x, tid = threadIdx.x;
    int lane = tid & 31, w = tid >> 5;
    uint32_t dbase = su32(db);

    if (tid < 64) { scs[tid] = g_scale[128+tid]; shs[tid] = g_shift[128+tid]; }
    if (tid < 128) { ssum[tid] = 0.f; ssq[tid] = 0.f; bias_s[tid] = bias[tid]; }
#pragma unroll
    for (int r = 0; r < 2; r++) { smx[r*256 + tid] = 0u; smn[r*256 + tid] = 0xFFFFFFFFu; }
    {
        const int4* s0 = (const int4*)g_w3s[0];
        const int4* s1 = (const int4*)g_w3s[1];
        int4* d0 = (int4*)(db + B_HI);
        int4* d1 = (int4*)(db + B_LO);
        for (int i = tid; i < 1152; i += 256) { d0[i] = s0[i]; d1[i] = s1[i]; }
    }
    __syncthreads();
    {
        int row = tid >> 1, l = tid & 1;
        unsigned char* ah = db + A_HI + row*144;
        unsigned char* al = db + A_LO + row*144;
        const float4* yp = (const float4*)(g_y2 + ((size_t)(blk*128 + row))*64 + l*32);
#pragma unroll
        for (int j = 0; j < 8; j++) {
            float4 v = yp[j];
            int col = l*32 + j*4;
            float a0 = fmaxf(v.x*scs[col]   + shs[col],   0.f);
            float a1 = fmaxf(v.y*scs[col+1] + shs[col+1], 0.f);
            float a2 = fmaxf(v.z*scs[col+2] + shs[col+2], 0.f);
            float a3 = fmaxf(v.w*scs[col+3] + shs[col+3], 0.f);
            uint32_t h01, l01, h23, l23;
            split_pair(a0, a1, h01, l01);
            split_pair(a2, a3, h23, l23);
            *(uint32_t*)(ah + col*2)     = h01;
            *(uint32_t*)(ah + col*2 + 4) = h23;
            *(uint32_t*)(al + col*2)     = l01;
            *(uint32_t*)(al + col*2 + 4) = l23;
        }
    }
    __syncthreads();

    float acc[16][4];
#pragma unroll
    for (int i = 0; i < 16; i++)
#pragma unroll
        for (int j = 0; j < 4; j++) acc[i][j] = 0.f;

    int g = lane >> 3, ln = lane & 7;
    uint32_t a_off = (uint32_t)(w*16 + ln + (g & 1)*8)*144 + (uint32_t)(g >> 1)*16;
    uint32_t b_off = (uint32_t)(ln + (g >> 1)*8)*144 + (uint32_t)(g & 1)*16;
    uint32_t AbH = dbase + A_HI + a_off, AbL = dbase + A_LO + a_off;
    uint32_t BbH = dbase + B_HI + b_off, BbL = dbase + B_LO + b_off;

#pragma unroll
    for (int ks = 0; ks < 4; ks++) {
        uint32_t ah[4], al[4];
        ldsm4(ah[0], ah[1], ah[2], ah[3], AbH + ks*32);
        ldsm4(al[0], al[1], al[2], al[3], AbL + ks*32);
#pragma unroll
        for (int np = 0; np < 8; np++) {
            uint32_t bh0, bh1, bh2, bh3, bl0, bl1, bl2, bl3;
            ldsm4(bh0, bh1, bh2, bh3, BbH + (uint32_t)np*16*144 + ks*32);
            ldsm4(bl0, bl1, bl2, bl3, BbL + (uint32_t)np*16*144 + ks*32);
            mma_bf16(acc[2*np],     ah, bh0, bh1);
            mma_bf16(acc[2*np + 1], ah, bh2, bh3);
            mma_bf16(acc[2*np],     ah, bl0, bl1);
            mma_bf16(acc[2*np + 1], ah, bl2, bl3);
            mma_bf16(acc[2*np],     al, bh0, bh1);
            mma_bf16(acc[2*np + 1], al, bh2, bh3);
        }
    }

    int q = lane & 3;
    int cb = (w >> 1) * 128;
#pragma unroll
    for (int nt = 0; nt < 16; nt++) {
        int c0 = nt*8 + q*2;
        float b0v = bias_s[c0], b1v = bias_s[c0+1];
        float v0 = acc[nt][0] + b0v, v1 = acc[nt][1] + b1v;
        float v2 = acc[nt][2] + b0v, v3 = acc[nt][3] + b1v;
        float mx0 = rmaxw(fmaxf(v0, v2)), mx1 = rmaxw(fmaxf(v1, v3));
        float mn0 = rminw(fminf(v0, v2)), mn1 = rminw(fminf(v1, v3));
        float s0 = rsum(v0 + v2), s1 = rsum(v1 + v3);
        float q0 = rsum(v0*v0 + v2*v2), q1 = rsum(v1*v1 + v3*v3);
        if (lane < 4) {
            atomicMax(&smx[cb + c0], fenc(mx0));  atomicMax(&smx[cb + c0 + 1], fenc(mx1));
            atomicMin(&smn[cb + c0], fenc(mn0));  atomicMin(&smn[cb + c0 + 1], fenc(mn1));
            atomicAdd(&ssum[c0], s0);  atomicAdd(&ssum[c0+1], s1);
            atomicAdd(&ssq [c0], q0);  atomicAdd(&ssq [c0+1], q1);
        }
    }
    __syncthreads();
    if (tid < 128) {
        atomicAdd(&g_sum[256 + tid], (double)ssum[tid]);
        atomicAdd(&g_sq [256 + tid], (double)ssq[tid]);
    }
#pragma unroll
    for (int r = 0; r < 2; r++) {
        int i = r*256 + tid;
        int cent = i >> 7, c = i & 127;
        size_t gi = ((size_t)(blk*4 + cent))*128 + c;
        g_mx[gi] = fdec(smx[i]);
        g_mn[gi] = fdec(smn[i]);
    }
}

// ---------------- BN finalize ----------------
__global__ void finalize_kernel(const float* __restrict__ g,
                                const float* __restrict__ beta,
                                int layer, int C) {
    int c = threadIdx.x;
    if (c < C) {
        double mean = g_sum[layer*128 + c] / (double)M_TOT;
        double var  = g_sq [layer*128 + c] / (double)M_TOT - mean*mean;
        float rstd = rsqrtf((float)var + 1e-5f);
        float sc = g[c] * rstd;
        g_scale[layer*128 + c] = sc;
        g_shift[layer*128 + c] = beta[c] - (float)mean * sc;
    }
}

// ---------------- final ----------------
__global__ __launch_bounds__(128) void final_kernel(float* __restrict__ out) {
    int m = blockIdx.x, o = threadIdx.x;
    float sc = g_scale[256 + o], sh = g_shift[256 + o];
    size_t gi = (size_t)m*128 + o;
    float y = (sc >= 0.f) ? g_mx[gi] : g_mn[gi];
    out[OUT_XYZ_ELEMS + gi] = fmaxf(y*sc + sh, 0.f);
}

extern "C" void kernel_launch(void* const* d_in, const int* in_sizes, int n_in,
                              void* d_out, int out_size) {
    const float* xyz   = (const float*)d_in[0];
    const float* pts   = (const float*)d_in[1];
    const float* w1    = (const float*)d_in[2];
    const float* b1    = (const float*)d_in[3];
    const float* g1    = (const float*)d_in[4];
    const float* beta1 = (const float*)d_in[5];
    const float* w2    = (const float*)d_in[6];
    const float* b2    = (const float*)d_in[7];
    const float* g2    = (const float*)d_in[8];
    const float* beta2 = (const float*)d_in[9];
    const float* w3    = (const float*)d_in[10];
    const float* b3    = (const float*)d_in[11];
    const float* g3    = (const float*)d_in[12];
    const float* beta3 = (const float*)d_in[13];
    float* out = (float*)d_out;

    cudaFuncSetAttribute(conv1_kernel, cudaFuncAttributeMaxDynamicSharedMemorySize, 67584);
    cudaFuncSetAttribute(conv2_kernel, cudaFuncAttributeMaxDynamicSharedMemorySize, 55296);
    cudaFuncSetAttribute(conv3_kernel, cudaFuncAttributeMaxDynamicSharedMemorySize, 73728);

    prep_kernel<<<(B_*N_ + 255)/256, 256>>>(xyz);
    wprep_kernel<<<32, 256>>>(w1, w2, w3);
    fps_kernel<<<B_, 256>>>(out);
    ballq_mask_kernel<<<1024, 256>>>();
    ballq_extract_kernel<<<NC/256, 256>>>();
    conv1_kernel<<<NC/4, 256, 67584>>>(pts, b1);
    finalize_kernel<<<1, 128>>>(g1, beta1, 0, 64);
    conv2_kernel<<<NC/4, 256, 55296>>>(b2);
    finalize_kernel<<<1, 128>>>(g2, beta2, 1, 64);
    conv3_kernel<<<NC/4, 256, 73728>>>(b3);
    finalize_kernel<<<1, 128>>>(g3, beta3, 2, 128);
    final_kernel<<<NC, 128>>>(out);
}